// round 5
// baseline (speedup 1.0000x reference)
#include <cuda_runtime.h>

// Problem constants: preds/target [B=8, C=21, H=512, W=512] float32.
#define NB 8
#define NC 21
#define HW (512 * 512)            // 262144 floats per (b,c) slab
#define HW4 (HW / 4)              // 65536 float4 per slab
#define TPB 256
#define VEC_PER_THREAD 8          // 8 float4 = 32 elements per thread
#define CHUNK_F4 (TPB * VEC_PER_THREAD)        // 2048 float4 per block
#define CHUNKS_PER_SLAB (HW4 / CHUNK_F4)       // 32
#define BLOCKS_PER_CLASS (NB * CHUNKS_PER_SLAB) // 256  (power of 2!)
#define GRID (NC * BLOCKS_PER_CLASS)            // 5376

// Scratch accumulators (no cudaMalloc allowed — __device__ globals).
__device__ int g_inter[NC];
__device__ int g_pred[NC];
__device__ int g_targ[NC];

__global__ void jaccard_zero_kernel() {
    int i = threadIdx.x;
    if (i < NC) {
        g_inter[i] = 0;
        g_pred[i]  = 0;
        g_targ[i]  = 0;
    }
}

// Two-phase streaming: batch-load 8 float4 from preds (one long run per
// warp), compress to a 32-bit mask, then batch-load 8 float4 from targ and
// combine with popc. Loads within a phase are fully independent -> MLP=8.
__global__ __launch_bounds__(TPB, 6)
void jaccard_count_kernel(const float4* __restrict__ preds,
                          const float4* __restrict__ targ) {
    const int blk = blockIdx.x;
    // All divisors are powers of two -> pure shifts/ands.
    const int c     = blk >> 8;            // / BLOCKS_PER_CLASS
    const int s     = blk & 255;
    const int b     = s >> 5;              // / CHUNKS_PER_SLAB
    const int chunk = s & 31;

    const size_t base = (size_t)b * (NC * (size_t)HW4)
                      + (size_t)c * HW4
                      + (size_t)chunk * CHUNK_F4
                      + threadIdx.x;

    // Phase 1: preds -> 32-bit mask (bit per element).
    unsigned int pmask = 0u;
#pragma unroll
    for (int j = 0; j < VEC_PER_THREAD; ++j) {
        const float4 p = __ldg(preds + base + (size_t)j * TPB);
        unsigned int m = (unsigned int)(p.x >= 0.5f)
                       | ((unsigned int)(p.y >= 0.5f) << 1)
                       | ((unsigned int)(p.z >= 0.5f) << 2)
                       | ((unsigned int)(p.w >= 0.5f) << 3);
        pmask |= m << (4 * j);
    }
    int ps = __popc(pmask);

    // Phase 2: targ -> combine with pmask nibbles.
    int inter = 0, ts = 0;
#pragma unroll
    for (int j = 0; j < VEC_PER_THREAD; ++j) {
        const float4 t = __ldg(targ + base + (size_t)j * TPB);
        unsigned int tm = (unsigned int)(t.x == 1.0f)
                        | ((unsigned int)(t.y == 1.0f) << 1)
                        | ((unsigned int)(t.z == 1.0f) << 2)
                        | ((unsigned int)(t.w == 1.0f) << 3);
        ts    += __popc(tm);
        inter += __popc(tm & ((pmask >> (4 * j)) & 0xFu));
    }

    // Warp reduction.
#pragma unroll
    for (int off = 16; off > 0; off >>= 1) {
        inter += __shfl_down_sync(0xffffffffu, inter, off);
        ps    += __shfl_down_sync(0xffffffffu, ps,    off);
        ts    += __shfl_down_sync(0xffffffffu, ts,    off);
    }

    __shared__ int s_i[TPB / 32], s_p[TPB / 32], s_t[TPB / 32];
    const int w = threadIdx.x >> 5;
    const int l = threadIdx.x & 31;
    if (l == 0) { s_i[w] = inter; s_p[w] = ps; s_t[w] = ts; }
    __syncthreads();

    if (threadIdx.x == 0) {
        int I = 0, P = 0, T = 0;
#pragma unroll
        for (int k = 0; k < TPB / 32; ++k) { I += s_i[k]; P += s_p[k]; T += s_t[k]; }
        atomicAdd(&g_inter[c], I);
        atomicAdd(&g_pred[c],  P);
        atomicAdd(&g_targ[c],  T);
    }
}

__global__ void jaccard_final_kernel(float* __restrict__ out) {
    int c = threadIdx.x;
    if (c < NC) {
        const float inter = (float)g_inter[c];
        const float uni   = (float)g_pred[c] + (float)g_targ[c] - inter;
        out[c] = (uni == 0.0f) ? __int_as_float(0x7fc00000)   // NaN
                               : inter / fmaxf(uni, 1.0f);
    }
}

extern "C" void kernel_launch(void* const* d_in, const int* in_sizes, int n_in,
                              void* d_out, int out_size) {
    const float4* preds = (const float4*)d_in[0];
    const float4* targ  = (const float4*)d_in[1];
    float* out          = (float*)d_out;

    jaccard_zero_kernel<<<1, 32>>>();
    jaccard_count_kernel<<<GRID, TPB>>>(preds, targ);
    jaccard_final_kernel<<<1, 32>>>(out);
}

// round 6
// speedup vs baseline: 1.0636x; 1.0636x over previous
#include <cuda_runtime.h>

// Problem constants: preds/target [B=8, C=21, H=512, W=512] float32.
// R1-R4 established: this workload plateaus at ~6.0 TB/s (73% of HBM spec)
// regardless of occupancy (33% vs 66%), fusion, grid size, or access pattern.
// This is the best-measured variant (R1, 58.75us) + __ldcs streaming hint.
#define NB 8
#define NC 21
#define HW (512 * 512)            // 262144 floats per (b,c) slab
#define HW4 (HW / 4)              // 65536 float4 per slab
#define CHUNKS_PER_SLAB 8
#define TPB 256
#define VEC_PER_THREAD (HW4 / CHUNKS_PER_SLAB / TPB)   // 32
#define BLOCKS_PER_CLASS (NB * CHUNKS_PER_SLAB)        // 64
#define GRID (NC * BLOCKS_PER_CLASS)                   // 1344

// Scratch accumulators (no cudaMalloc allowed — __device__ globals).
__device__ int g_inter[NC];
__device__ int g_pred[NC];
__device__ int g_targ[NC];

__global__ void jaccard_zero_kernel() {
    int i = threadIdx.x;
    if (i < NC) {
        g_inter[i] = 0;
        g_pred[i]  = 0;
        g_targ[i]  = 0;
    }
}

__global__ __launch_bounds__(TPB, 1)
void jaccard_count_kernel(const float4* __restrict__ preds,
                          const float4* __restrict__ targ) {
    const int blk   = blockIdx.x;
    const int c     = blk / BLOCKS_PER_CLASS;
    const int s     = blk % BLOCKS_PER_CLASS;
    const int b     = s / CHUNKS_PER_SLAB;
    const int chunk = s % CHUNKS_PER_SLAB;

    // Base offset of this block's contiguous region, in float4 units.
    const size_t base = (size_t)b * (NC * (size_t)HW4)
                      + (size_t)c * HW4
                      + (size_t)chunk * (HW4 / CHUNKS_PER_SLAB)
                      + threadIdx.x;

    int inter = 0, ps = 0, ts = 0;

#pragma unroll 8
    for (int j = 0; j < VEC_PER_THREAD; ++j) {
        const size_t idx = base + (size_t)j * TPB;
        // Streaming loads (evict-first): zero reuse, keep L2 pressure minimal.
        const float4 p = __ldcs(preds + idx);
        const float4 t = __ldcs(targ + idx);

        const int pm0 = (p.x >= 0.5f), pm1 = (p.y >= 0.5f);
        const int pm2 = (p.z >= 0.5f), pm3 = (p.w >= 0.5f);
        const int tm0 = (t.x == 1.0f), tm1 = (t.y == 1.0f);
        const int tm2 = (t.z == 1.0f), tm3 = (t.w == 1.0f);

        ps    += pm0 + pm1 + pm2 + pm3;
        ts    += tm0 + tm1 + tm2 + tm3;
        inter += (pm0 & tm0) + (pm1 & tm1) + (pm2 & tm2) + (pm3 & tm3);
    }

    // Warp reduction.
#pragma unroll
    for (int off = 16; off > 0; off >>= 1) {
        inter += __shfl_down_sync(0xffffffffu, inter, off);
        ps    += __shfl_down_sync(0xffffffffu, ps,    off);
        ts    += __shfl_down_sync(0xffffffffu, ts,    off);
    }

    __shared__ int s_i[TPB / 32], s_p[TPB / 32], s_t[TPB / 32];
    const int w = threadIdx.x >> 5;
    const int l = threadIdx.x & 31;
    if (l == 0) { s_i[w] = inter; s_p[w] = ps; s_t[w] = ts; }
    __syncthreads();

    if (threadIdx.x == 0) {
        int I = 0, P = 0, T = 0;
#pragma unroll
        for (int k = 0; k < TPB / 32; ++k) { I += s_i[k]; P += s_p[k]; T += s_t[k]; }
        atomicAdd(&g_inter[c], I);
        atomicAdd(&g_pred[c],  P);
        atomicAdd(&g_targ[c],  T);
    }
}

__global__ void jaccard_final_kernel(float* __restrict__ out) {
    int c = threadIdx.x;
    if (c < NC) {
        const float inter = (float)g_inter[c];
        const float uni   = (float)g_pred[c] + (float)g_targ[c] - inter;
        out[c] = (uni == 0.0f) ? __int_as_float(0x7fc00000)   // NaN
                               : inter / fmaxf(uni, 1.0f);
    }
}

extern "C" void kernel_launch(void* const* d_in, const int* in_sizes, int n_in,
                              void* d_out, int out_size) {
    const float4* preds = (const float4*)d_in[0];
    const float4* targ  = (const float4*)d_in[1];
    float* out          = (float*)d_out;

    jaccard_zero_kernel<<<1, 32>>>();
    jaccard_count_kernel<<<GRID, TPB>>>(preds, targ);
    jaccard_final_kernel<<<1, 32>>>(out);
}

// round 7
// speedup vs baseline: 1.0725x; 1.0084x over previous
#include <cuda_runtime.h>

// Problem constants: preds/target [B=8, C=21, H=512, W=512] float32.
// R1-R5 established: this workload plateaus at ~6.1 TB/s regardless of
// occupancy (33% vs 66%), fusion, grid size, or access pattern. Best variant:
// R1 structure + __ldcs streaming loads (57.8us). This round removes the
// zero-kernel graph node by folding the counter reset into the final kernel
// (globals are zero at load; final resets them after reading, so every graph
// replay sees zeroed counters). Count kernel is byte-identical to the winner.
#define NB 8
#define NC 21
#define HW (512 * 512)            // 262144 floats per (b,c) slab
#define HW4 (HW / 4)              // 65536 float4 per slab
#define CHUNKS_PER_SLAB 8
#define TPB 256
#define VEC_PER_THREAD (HW4 / CHUNKS_PER_SLAB / TPB)   // 32
#define BLOCKS_PER_CLASS (NB * CHUNKS_PER_SLAB)        // 64
#define GRID (NC * BLOCKS_PER_CLASS)                   // 1344

// Scratch accumulators (no cudaMalloc allowed — __device__ globals).
// Zero-initialized at module load; jaccard_final_kernel re-zeroes them after
// every read, so each replay of the captured graph starts from zero.
__device__ int g_inter[NC];
__device__ int g_pred[NC];
__device__ int g_targ[NC];

__global__ __launch_bounds__(TPB, 1)
void jaccard_count_kernel(const float4* __restrict__ preds,
                          const float4* __restrict__ targ) {
    const int blk   = blockIdx.x;
    const int c     = blk / BLOCKS_PER_CLASS;
    const int s     = blk % BLOCKS_PER_CLASS;
    const int b     = s / CHUNKS_PER_SLAB;
    const int chunk = s % CHUNKS_PER_SLAB;

    // Base offset of this block's contiguous region, in float4 units.
    const size_t base = (size_t)b * (NC * (size_t)HW4)
                      + (size_t)c * HW4
                      + (size_t)chunk * (HW4 / CHUNKS_PER_SLAB)
                      + threadIdx.x;

    int inter = 0, ps = 0, ts = 0;

#pragma unroll 8
    for (int j = 0; j < VEC_PER_THREAD; ++j) {
        const size_t idx = base + (size_t)j * TPB;
        // Streaming loads (evict-first): zero reuse, keep L2 pressure minimal.
        const float4 p = __ldcs(preds + idx);
        const float4 t = __ldcs(targ + idx);

        const int pm0 = (p.x >= 0.5f), pm1 = (p.y >= 0.5f);
        const int pm2 = (p.z >= 0.5f), pm3 = (p.w >= 0.5f);
        const int tm0 = (t.x == 1.0f), tm1 = (t.y == 1.0f);
        const int tm2 = (t.z == 1.0f), tm3 = (t.w == 1.0f);

        ps    += pm0 + pm1 + pm2 + pm3;
        ts    += tm0 + tm1 + tm2 + tm3;
        inter += (pm0 & tm0) + (pm1 & tm1) + (pm2 & tm2) + (pm3 & tm3);
    }

    // Warp reduction.
#pragma unroll
    for (int off = 16; off > 0; off >>= 1) {
        inter += __shfl_down_sync(0xffffffffu, inter, off);
        ps    += __shfl_down_sync(0xffffffffu, ps,    off);
        ts    += __shfl_down_sync(0xffffffffu, ts,    off);
    }

    __shared__ int s_i[TPB / 32], s_p[TPB / 32], s_t[TPB / 32];
    const int w = threadIdx.x >> 5;
    const int l = threadIdx.x & 31;
    if (l == 0) { s_i[w] = inter; s_p[w] = ps; s_t[w] = ts; }
    __syncthreads();

    if (threadIdx.x == 0) {
        int I = 0, P = 0, T = 0;
#pragma unroll
        for (int k = 0; k < TPB / 32; ++k) { I += s_i[k]; P += s_p[k]; T += s_t[k]; }
        atomicAdd(&g_inter[c], I);
        atomicAdd(&g_pred[c],  P);
        atomicAdd(&g_targ[c],  T);
    }
}

__global__ void jaccard_final_kernel(float* __restrict__ out) {
    int c = threadIdx.x;
    if (c < NC) {
        const float inter = (float)g_inter[c];
        const float uni   = (float)g_pred[c] + (float)g_targ[c] - inter;
        out[c] = (uni == 0.0f) ? __int_as_float(0x7fc00000)   // NaN
                               : inter / fmaxf(uni, 1.0f);
        // Reset counters for the next graph replay (graph edge serializes
        // this before the next replay's count kernel starts).
        g_inter[c] = 0;
        g_pred[c]  = 0;
        g_targ[c]  = 0;
    }
}

extern "C" void kernel_launch(void* const* d_in, const int* in_sizes, int n_in,
                              void* d_out, int out_size) {
    const float4* preds = (const float4*)d_in[0];
    const float4* targ  = (const float4*)d_in[1];
    float* out          = (float*)d_out;

    jaccard_count_kernel<<<GRID, TPB>>>(preds, targ);
    jaccard_final_kernel<<<1, 32>>>(out);
}